// round 16
// baseline (speedup 1.0000x reference)
#include <cuda_runtime.h>
#include <stdint.h>

// ---------------- problem constants ----------------
namespace {
constexpr int NB   = 4;
constexpr int CH   = 128;
constexpr int NSP  = 32768;
constexpr int GRP  = 4;
constexpr int NH   = 4;
constexpr int HDIM = 32;
constexpr int QKVC = 3 * CH;              // 384
constexpr int GELEM = (CH / GRP) * NSP;   // 1,048,576 per (b,g)
constexpr int RED_CHUNKS = 64;
constexpr int NT = NSP / 128;             // 256 n-tiles
constexpr int CTXSZ = NB * NH * HDIM * 33;// 16896

// gemm0 smem layout (floats): K-slice 16, 4 rotating B stages, 512 thr
constexpr int G0_AS   = 0;                // [256][132]          (33792)
constexpr int G0_BS   = 33792;            // [4][16][136]        (8704)
constexpr int G0_ZP   = 42496;            // [128][4]            (512)
constexpr int G0_SMEM = 43008;            // 172032 B
constexpr int G0_EP   = 0;                // epilogue: [128][132]
constexpr int G0_VP   = 16896;            // epilogue: [128][132]
constexpr int G0_PS   = 33792;            // epilogue: ctx K-half partials (8192 floats)

// gemm1 smem layout (floats)
constexpr int G1_AS   = 0;                // [128][132]
constexpr int G1_BS   = 16896;            // [4][16][136]
constexpr int G1_SMEM = 25600;            // 102400 B
}

// ---------------- device scratch ----------------
__device__ float g_part[NB * GRP * RED_CHUNKS * 2];
__device__ float g_W1[NB * QKVC * CH];
__device__ float g_b1[NB * QKVC];
__device__ float g_ctxp[(size_t)NT * CTXSZ];
__device__ float g_ctx2[16 * CTXSZ];
__device__ float g_ctx[CTXSZ];
__device__ float g_M[NB * CH * CH];
__device__ float g_F[NB * CH * CH];
__device__ float g_fb[NB * CH];

// ---------------- helpers ----------------
__device__ __forceinline__ uint32_t f2tf(float f) {
    uint32_t r; asm("cvt.rna.tf32.f32 %0, %1;" : "=r"(r) : "f"(f)); return r;
}
__device__ __forceinline__ float tf32f(float f) {
    return __uint_as_float(f2tf(f));
}
__device__ __forceinline__ void mma8(float* c, uint32_t a0, uint32_t a1,
                                     uint32_t a2, uint32_t a3,
                                     uint32_t b0, uint32_t b1) {
    asm volatile(
        "mma.sync.aligned.m16n8k8.row.col.f32.tf32.tf32.f32 "
        "{%0,%1,%2,%3},{%4,%5,%6,%7},{%8,%9},{%0,%1,%2,%3};"
        : "+f"(c[0]), "+f"(c[1]), "+f"(c[2]), "+f"(c[3])
        : "r"(a0), "r"(a1), "r"(a2), "r"(a3), "r"(b0), "r"(b1));
}
// a0..a3 of tf32 m16n8k8 A-fragment in one instruction
__device__ __forceinline__ void ldsm_x4(uint32_t& d0, uint32_t& d1,
                                        uint32_t& d2, uint32_t& d3, uint32_t addr) {
    asm volatile("ldmatrix.sync.aligned.m8n8.x4.shared.b16 {%0,%1,%2,%3}, [%4];"
                 : "=r"(d0), "=r"(d1), "=r"(d2), "=r"(d3) : "r"(addr));
}
// x2 variant (two 8x8 matrices)
__device__ __forceinline__ void ldsm_x2(uint32_t& d0, uint32_t& d1, uint32_t addr) {
    asm volatile("ldmatrix.sync.aligned.m8n8.x2.shared.b16 {%0,%1}, [%2];"
                 : "=r"(d0), "=r"(d1) : "r"(addr));
}
__device__ __forceinline__ void cp_async16(uint32_t smem_byte, const void* g) {
    asm volatile("cp.async.ca.shared.global [%0], [%1], 16;"
                 :: "r"(smem_byte), "l"(g));
}
__device__ __forceinline__ void cp_commit() {
    asm volatile("cp.async.commit_group;");
}
template <int N>
__device__ __forceinline__ void cp_wait() {
    asm volatile("cp.async.wait_group %0;" :: "n"(N));
}
// wait so that buffer k0 (of 8, last commit at k0=5+3) is retired
__device__ __forceinline__ void cp_wait_for(int k0) {
    if (k0 < 6)      cp_wait<2>();
    else if (k0 == 6) cp_wait<1>();
    else              cp_wait<0>();
}

// ---------------- 0) profiling shim (aligns gemm0 with ncu capture window) ----------------
__global__ void shim_k() {}

// ---------------- 1) groupnorm stats (1024 blocks) ----------------
__global__ void reduce_k(const float* __restrict__ x) {
    int bg = blockIdx.x >> 6;
    int chunk = blockIdx.x & 63;
    const float4* p = reinterpret_cast<const float4*>(
        x + (size_t)bg * GELEM + (size_t)chunk * (GELEM / RED_CHUNKS));
    int t = threadIdx.x;
    float s = 0.f, q = 0.f;
#pragma unroll
    for (int i = 0; i < 16; i++) {
        float4 v = p[t + i * 256];
        s += (v.x + v.y) + (v.z + v.w);
        q += v.x * v.x + v.y * v.y + v.z * v.z + v.w * v.w;
    }
    for (int off = 16; off; off >>= 1) {
        s += __shfl_down_sync(0xffffffffu, s, off);
        q += __shfl_down_sync(0xffffffffu, q, off);
    }
    __shared__ float ss[8], sq[8];
    if ((t & 31) == 0) { ss[t >> 5] = s; sq[t >> 5] = q; }
    __syncthreads();
    if (t == 0) {
        float S = 0.f, Q = 0.f;
        for (int i = 0; i < 8; i++) { S += ss[i]; Q += sq[i]; }
        g_part[blockIdx.x * 2]     = S;
        g_part[blockIdx.x * 2 + 1] = Q;
    }
}

// ---------------- 2) fold gn into qkv weight/bias (W tf32-RNA pre-rounded) ----------------
__global__ void prep_k(const float* __restrict__ qkvw,
                       const float* __restrict__ gnw,
                       const float* __restrict__ gnb) {
    int o = blockIdx.x, b = blockIdx.y, c = threadIdx.x;
    int g = c >> 5;
    int bg = b * GRP + g;
    float S = 0.f, Q = 0.f;
#pragma unroll 8
    for (int ch = 0; ch < RED_CHUNKS; ch++) {
        S += g_part[(bg * RED_CHUNKS + ch) * 2];
        Q += g_part[(bg * RED_CHUNKS + ch) * 2 + 1];
    }
    const float inv = 1.0f / (float)GELEM;
    float mean = S * inv;
    float var  = Q * inv - mean * mean;
    float rstd = rsqrtf(var + 1e-5f);
    float s = rstd * gnw[c];
    float t = gnb[c] - mean * s;
    float w = qkvw[o * CH + c];
    g_W1[(b * QKVC + o) * CH + c] = tf32f(w * s);
    __shared__ float red[CH];
    red[c] = w * t;
    __syncthreads();
    for (int off = 64; off; off >>= 1) {
        if (c < off) red[c] += red[c + off];
        __syncthreads();
    }
    if (c == 0) g_b1[b * QKVC + o] = red[0];
}

// ---------------- 3) fused kv-gemm + exp + ctx partials (512 thr, ldsm) ----------------
__global__ void __launch_bounds__(512) gemm0_k(const float* __restrict__ x) {
    extern __shared__ float smem[];
    float* As = smem + G0_AS;
    float* Bs = smem + G0_BS;
    float* Zp = smem + G0_ZP;
    float* Ep = smem + G0_EP;
    float* Vp = smem + G0_VP;
    float* Ps = smem + G0_PS;

    int b = blockIdx.z;
    int tN = blockIdx.x * 128;
    const float* A = g_W1 + (size_t)(b * QKVC + CH) * CH;   // k,v rows (tf32 pre-rounded)
    const float* B = x + (size_t)b * CH * NSP;
    int tid = threadIdx.x, lane = tid & 31, w = tid >> 5;   // w: 0..15
    int wm = w >> 2, wn = w & 3;               // 4 m-rows x 4 n-cols
    int q = lane >> 2, m = lane & 3;

    uint32_t as_b = (uint32_t)__cvta_generic_to_shared(As);
    uint32_t bs_b = (uint32_t)__cvta_generic_to_shared(Bs);

    // A preload via cp.async (already RNA-rounded in global) -> part of group 0
#pragma unroll 4
    for (int i = 0; i < 16; i++) {
        int f = tid + i * 512;
        int r = f >> 5, c4 = (f & 31) * 4;
        cp_async16(as_b + (uint32_t)(r * 132 + c4) * 4u, &A[r * CH + c4]);
    }

    int br = tid >> 5, bc = (tid & 31) * 4;     // 512 thr -> one float4 each
#define CPB(t) do { int kr = (t) * 16; uint32_t dst = bs_b + (uint32_t)(((t) & 3) * 2176) * 4u; \
        cp_async16(dst + (uint32_t)(br * 136 + bc) * 4u, &B[(size_t)(kr + br) * NSP + tN + bc]); } while (0)

    CPB(0); cp_commit();          // group0 = A + B0
    CPB(1); cp_commit();
    CPB(2); cp_commit();

    // ldmatrix lane addressing: row = r0 + (lane&15), col = (lane>>4)*4
    int rl = lane & 15, cl = (lane >> 4) * 4;
    uint32_t aaddr[4];
#pragma unroll
    for (int mt = 0; mt < 4; mt++)
        aaddr[mt] = as_b + (uint32_t)((wm * 64 + mt * 16 + rl) * 132 + cl) * 4u;

    float acc[4][4][4];
#pragma unroll
    for (int mt = 0; mt < 4; mt++)
#pragma unroll
        for (int nt = 0; nt < 4; nt++)
#pragma unroll
            for (int i = 0; i < 4; i++) acc[mt][nt][i] = 0.f;

#pragma unroll
    for (int k0 = 0; k0 < 8; k0++) {
        cp_wait_for(k0);
        __syncthreads();
        if (k0 < 5) { CPB(k0 + 3); cp_commit(); }
        const float* Bb = Bs + (k0 & 3) * 2176;
#pragma unroll
        for (int ks = 0; ks < 16; ks += 8) {
            uint32_t a[4][4];
#pragma unroll
            for (int mt = 0; mt < 4; mt++)
                ldsm_x4(a[mt][0], a[mt][1], a[mt][2], a[mt][3],
                        aaddr[mt] + (uint32_t)(k0 * 16 + ks) * 4u);
#pragma unroll
            for (int nt = 0; nt < 4; nt++) {
                int col = wn * 32 + nt * 8 + q;
                uint32_t b0 = f2tf(Bb[(ks + m) * 136 + col]);
                uint32_t b1 = f2tf(Bb[(ks + 4 + m) * 136 + col]);
#pragma unroll
                for (int mt = 0; mt < 4; mt++)
                    mma8(acc[mt][nt], a[mt][0], a[mt][1], a[mt][2], a[mt][3], b0, b1);
            }
        }
    }
#undef CPB

    // bias (+exp on k rows) + Z partials from registers
    const float* bias = g_b1 + b * QKVC + CH;
    float zlo[4], zhi[4];
#pragma unroll
    for (int mt = 0; mt < 4; mt++) {
        int r0 = wm * 64 + mt * 16 + q;
        float bv0 = bias[r0], bv1 = bias[r0 + 8];
        zlo[mt] = 0.f; zhi[mt] = 0.f;
#pragma unroll
        for (int nt = 0; nt < 4; nt++) {
            if (wm < 2) {   // k rows -> exp
                acc[mt][nt][0] = __expf(acc[mt][nt][0] + bv0);
                acc[mt][nt][1] = __expf(acc[mt][nt][1] + bv0);
                acc[mt][nt][2] = __expf(acc[mt][nt][2] + bv1);
                acc[mt][nt][3] = __expf(acc[mt][nt][3] + bv1);
                zlo[mt] += acc[mt][nt][0] + acc[mt][nt][1];
                zhi[mt] += acc[mt][nt][2] + acc[mt][nt][3];
            } else {        // v rows
                acc[mt][nt][0] += bv0; acc[mt][nt][1] += bv0;
                acc[mt][nt][2] += bv1; acc[mt][nt][3] += bv1;
            }
        }
        if (wm < 2) {       // quad-reduce across the 4 col-lanes
            zlo[mt] += __shfl_xor_sync(0xffffffffu, zlo[mt], 1);
            zlo[mt] += __shfl_xor_sync(0xffffffffu, zlo[mt], 2);
            zhi[mt] += __shfl_xor_sync(0xffffffffu, zhi[mt], 1);
            zhi[mt] += __shfl_xor_sync(0xffffffffu, zhi[mt], 2);
        }
    }

    __syncthreads();        // As dead; reuse as Ep/Vp

    // scatter E (exp(k), tf32-rounded), V (tf32-rounded), Z partials
#pragma unroll
    for (int mt = 0; mt < 4; mt++) {
        int r = wm * 64 + mt * 16 + q;          // 0..255
        float* T = (r < 128) ? (Ep + r * 132) : (Vp + (r - 128) * 132);
#pragma unroll
        for (int nt = 0; nt < 4; nt++) {
            int cc = wn * 32 + nt * 8 + 2 * m;
            float2 lo = make_float2(tf32f(acc[mt][nt][0]), tf32f(acc[mt][nt][1]));
            float2 hi = make_float2(tf32f(acc[mt][nt][2]), tf32f(acc[mt][nt][3]));
            *reinterpret_cast<float2*>(T + cc)           = lo;
            *reinterpret_cast<float2*>(T + 8 * 132 + cc) = hi;
        }
        if (wm < 2 && m == 0) {
            Zp[r * 4 + wn]       = zlo[mt];
            Zp[(r + 8) * 4 + wn] = zhi[mt];
        }
    }
    __syncthreads();

    float* pbase = g_ctxp + (size_t)blockIdx.x * CTXSZ;

    // Z: combine the four col-stripe partials, write
    if (tid < 128) {
        int h = tid >> 5, d = tid & 31;
        pbase[(size_t)((b * NH + h) * HDIM + d) * 33 + 32] =
            (Zp[tid * 4] + Zp[tid * 4 + 1]) + (Zp[tid * 4 + 2] + Zp[tid * 4 + 3]);
    }

    // ctx mma: ALL 16 warps. warp = (wg, kh): wg 0..7 -> head h=wg>>1, row-half mh=wg&1;
    // kh 0..1 -> K half (ks 0..63 / 64..127). kh=1 stores partials to Ps; kh=0 adds.
    float c4[4][4];
    int wg = w & 7, kh = w >> 3;
    {
        int h = wg >> 1, mh = wg & 1;
        const float* Eh = Ep + h * 32 * 132;
        const float* Vh = Vp + h * 32 * 132;
#pragma unroll
        for (int nt = 0; nt < 4; nt++)
#pragma unroll
            for (int i = 0; i < 4; i++) c4[nt][i] = 0.f;
#pragma unroll
        for (int kk = 0; kk < 64; kk += 8) {
            int ks = kh * 64 + kk;
            int ar = mh * 16 + q;
            uint32_t a0 = __float_as_uint(Eh[ar * 132 + ks + m]);
            uint32_t a1 = __float_as_uint(Eh[(ar + 8) * 132 + ks + m]);
            uint32_t a2 = __float_as_uint(Eh[ar * 132 + ks + m + 4]);
            uint32_t a3 = __float_as_uint(Eh[(ar + 8) * 132 + ks + m + 4]);
#pragma unroll
            for (int nt = 0; nt < 4; nt++) {
                int ec = nt * 8 + q;
                uint32_t b0 = __float_as_uint(Vh[ec * 132 + ks + m]);
                uint32_t b1 = __float_as_uint(Vh[ec * 132 + ks + 4 + m]);
                mma8(c4[nt], a0, a1, a2, a3, b0, b1);
            }
        }
        if (kh == 1) {      // store upper-K partials
            float* pp = Ps + (wg * 32 + lane) * 16;
#pragma unroll
            for (int nt = 0; nt < 4; nt++) {
                float4 v = make_float4(c4[nt][0], c4[nt][1], c4[nt][2], c4[nt][3]);
                *reinterpret_cast<float4*>(pp + nt * 4) = v;
            }
        }
    }
    __syncthreads();
    if (kh == 0) {
        int h = wg >> 1, mh = wg & 1;
        const float* pp = Ps + (wg * 32 + lane) * 16;
        float* ph = pbase + (size_t)((b * NH + h) * HDIM) * 33;
        int dr = mh * 16 + q;
#pragma unroll
        for (int nt = 0; nt < 4; nt++) {
            float4 v = *reinterpret_cast<const float4*>(pp + nt * 4);
            int ec = nt * 8 + 2 * m;
            ph[dr * 33 + ec]           = c4[nt][0] + v.x;
            ph[dr * 33 + ec + 1]       = c4[nt][1] + v.y;
            ph[(dr + 8) * 33 + ec]     = c4[nt][2] + v.z;
            ph[(dr + 8) * 33 + ec + 1] = c4[nt][3] + v.w;
        }
    }
}

// ---------------- 4) combine ctx partials: two stages (16-way, scalar) ----------------
__global__ void combineA_k() {
    int t = blockIdx.x * 256 + threadIdx.x;
    int g = blockIdx.y;
    const float* p = g_ctxp + (size_t)(g * 16) * CTXSZ + t;
    float s0 = 0.f, s1 = 0.f, s2 = 0.f, s3 = 0.f;
#pragma unroll
    for (int c = 0; c < 16; c += 4) {
        s0 += p[(size_t)c * CTXSZ];
        s1 += p[(size_t)(c + 1) * CTXSZ];
        s2 += p[(size_t)(c + 2) * CTXSZ];
        s3 += p[(size_t)(c + 3) * CTXSZ];
    }
    g_ctx2[g * CTXSZ + t] = (s0 + s1) + (s2 + s3);
}
__global__ void combineB_k() {
    int t = blockIdx.x * 256 + threadIdx.x;
    float s = 0.f;
#pragma unroll
    for (int g = 0; g < 16; g++) s += g_ctx2[g * CTXSZ + t];
    g_ctx[t] = s;
}

// ---------------- 5) M = out_w folded through normalized ctx ----------------
__global__ void fold1_k(const float* __restrict__ outw) {
    int o = blockIdx.x, b = blockIdx.y, hd = threadIdx.x;
    int h = hd >> 5, d = hd & 31;
    __shared__ float sOW[CH];
    sOW[hd] = outw[o * CH + hd];
    __syncthreads();
    const float* nm = g_ctx + (size_t)((b * NH + h) * HDIM + d) * 33;
    float acc = 0.f;
#pragma unroll
    for (int e = 0; e < HDIM; e++) acc += sOW[h * HDIM + e] * nm[e];
    g_M[(b * CH + o) * CH + hd] = acc / nm[32];
}

// ---------------- 6) F = M @ Wq' (tf32 pre-rounded), fb = M @ bq' + out_bias ----------------
__global__ void fold2_k(const float* __restrict__ outb) {
    int o = blockIdx.x, b = blockIdx.y, c = threadIdx.x;
    __shared__ float sM[CH];
    __shared__ float red[CH];
    sM[c] = g_M[(size_t)(b * CH + o) * CH + c];
    __syncthreads();
    const float* Wq = g_W1 + (size_t)b * QKVC * CH;
    float acc = 0.f;
#pragma unroll 8
    for (int k = 0; k < CH; k++) acc += sM[k] * Wq[k * CH + c];
    g_F[(size_t)(b * CH + o) * CH + c] = tf32f(acc);
    red[c] = sM[c] * g_b1[b * QKVC + c];
    __syncthreads();
    for (int off = 64; off; off >>= 1) {
        if (c < off) red[c] += red[c + off];
        __syncthreads();
    }
    if (c == 0) g_fb[b * CH + o] = red[0] + outb[o];
}

// ---------------- 7) out = F @ x + fb + x (512 thr, 2 CTA/SM) ----------------
__global__ void __launch_bounds__(512, 2) gemm1_k(const float* __restrict__ x,
                                                  float* __restrict__ out) {
    extern __shared__ float smem[];
    float* As = smem + G1_AS;
    float* Bs = smem + G1_BS;

    int b = blockIdx.z;
    int tN = blockIdx.x * 128;
    const float* A = g_F + (size_t)b * CH * CH;   // tf32 pre-rounded
    const float* B = x + (size_t)b * CH * NSP;
    float* Co = out + (size_t)b * CH * NSP;
    int tid = threadIdx.x, lane = tid & 31, w = tid >> 5;   // w 0..15
    int wm = w >> 2, wn = w & 3;               // 4 m-quarters x 4 n-cols, 32x32 per warp
    int q = lane >> 2, m = lane & 3;

    uint32_t as_b = (uint32_t)__cvta_generic_to_shared(As);
    uint32_t bs_b = (uint32_t)__cvta_generic_to_shared(Bs);

    // A preload via cp.async (128x128 -> 512 thr: 8 float4 each)
#pragma unroll 4
    for (int i = 0; i < 8; i++) {
        int f = tid + i * 512;
        int r = f >> 5, c4 = (f & 31) * 4;
        cp_async16(as_b + (uint32_t)(r * 132 + c4) * 4u, &A[r * CH + c4]);
    }

    int br = tid >> 5, bc = (tid & 31) * 4;     // 512 thr -> one float4 per stage
#define CPB(t) do { int kr = (t) * 16; uint32_t dst = bs_b + (uint32_t)(((t) & 3) * 2176) * 4u; \
        cp_async16(dst + (uint32_t)(br * 136 + bc) * 4u, &B[(size_t)(kr + br) * NSP + tN + bc]); } while (0)

    CPB(0); cp_commit();
    CPB(1); cp_commit();
    CPB(2); cp_commit();

    int rl = lane & 15, cl = (lane >> 4) * 4;
    uint32_t aaddr[2];
#pragma unroll
    for (int mt = 0; mt < 2; mt++)
        aaddr[mt] = as_b + (uint32_t)((wm * 32 + mt * 16 + rl) * 132 + cl) * 4u;

    float acc[2][4][4];
#pragma unroll
    for (int mt = 0; mt < 2; mt++)
#pragma unroll
        for (int nt = 0; nt < 4; nt++)
#pragma unroll
            for (int i = 0; i < 4; i++) acc[mt][nt][i] = 0.f;

#pragma unroll
    for (int k0 = 0; k0 < 8; k0++) {
        cp_wait_for(k0);
        __syncthreads();
        if (k0 < 5) { CPB(k0 + 3); cp_commit(); }
        const float* Bb = Bs + (k0 & 3) * 2176;
#pragma unroll
        for (int ks = 0; ks < 16; ks += 8) {
            uint32_t a[2][4];
#pragma unroll
            for (int mt = 0; mt < 2; mt++)
                ldsm_x4(a[mt][0], a[mt][1], a[mt][2], a[mt][3],
                        aaddr[mt] + (uint32_t)(k0 * 16 + ks) * 4u);
#pragma unroll
            for (int nt = 0; nt < 4; nt++) {
                int col = wn * 32 + nt * 8 + q;
                uint32_t b0 = f2tf(Bb[(ks + m) * 136 + col]);
                uint32_t b1 = f2tf(Bb[(ks + 4 + m) * 136 + col]);
                mma8(acc[0][nt], a[0][0], a[0][1], a[0][2], a[0][3], b0, b1);
                mma8(acc[1][nt], a[1][0], a[1][1], a[1][2], a[1][3], b0, b1);
            }
        }
    }
#undef CPB

#pragma unroll
    for (int mt = 0; mt < 2; mt++) {
        int r0 = wm * 32 + mt * 16 + q;
        float bv0 = g_fb[b * CH + r0], bv1 = g_fb[b * CH + r0 + 8];
#pragma unroll
        for (int nt = 0; nt < 4; nt++) {
            int cc = wn * 32 + nt * 8 + 2 * m;
            size_t o0 = (size_t)r0 * NSP + tN + cc;
            size_t o1 = (size_t)(r0 + 8) * NSP + tN + cc;
            float2 x0 = *reinterpret_cast<const float2*>(&B[o0]);
            float2 x1 = *reinterpret_cast<const float2*>(&B[o1]);
            float2 r0v = { acc[mt][nt][0] + bv0 + x0.x, acc[mt][nt][1] + bv0 + x0.y };
            float2 r1v = { acc[mt][nt][2] + bv1 + x1.x, acc[mt][nt][3] + bv1 + x1.y };
            *reinterpret_cast<float2*>(&Co[o0]) = r0v;
            *reinterpret_cast<float2*>(&Co[o1]) = r1v;
        }
    }
}

// ---------------- launch ----------------
extern "C" void kernel_launch(void* const* d_in, const int* in_sizes, int n_in,
                              void* d_out, int out_size) {
    (void)in_sizes; (void)n_in; (void)out_size;
    const float* x    = (const float*)d_in[0];
    const float* gnw  = (const float*)d_in[1];
    const float* gnb  = (const float*)d_in[2];
    const float* qkvw = (const float*)d_in[3];
    const float* outw = (const float*)d_in[4];
    const float* outb = (const float*)d_in[5];
    float* out = (float*)d_out;

    cudaFuncSetAttribute(gemm0_k, cudaFuncAttributeMaxDynamicSharedMemorySize,
                         G0_SMEM * sizeof(float));
    cudaFuncSetAttribute(gemm1_k, cudaFuncAttributeMaxDynamicSharedMemorySize,
                         G1_SMEM * sizeof(float));

    reduce_k<<<NB * GRP * RED_CHUNKS, 256>>>(x);
    prep_k<<<dim3(QKVC, NB), CH>>>(qkvw, gnw, gnb);
    shim_k<<<1, 32>>>();      // aligns gemm0 with ncu's fixed capture window
    gemm0_k<<<dim3(NT, 1, NB), 512, G0_SMEM * sizeof(float)>>>(x);
    combineA_k<<<dim3(CTXSZ / 256, 16), 256>>>();
    combineB_k<<<CTXSZ / 256, 256>>>();
    fold1_k<<<dim3(CH, NB), CH>>>(outw);
    fold2_k<<<dim3(CH, NB), CH>>>(outb);
    gemm1_k<<<dim3(NT, 1, NB), 512, G1_SMEM * sizeof(float)>>>(x, out);
}

// round 17
// speedup vs baseline: 1.0814x; 1.0814x over previous
#include <cuda_runtime.h>
#include <stdint.h>

// ---------------- problem constants ----------------
namespace {
constexpr int NB   = 4;
constexpr int CH   = 128;
constexpr int NSP  = 32768;
constexpr int GRP  = 4;
constexpr int NH   = 4;
constexpr int HDIM = 32;
constexpr int QKVC = 3 * CH;              // 384
constexpr int GELEM = (CH / GRP) * NSP;   // 1,048,576 per (b,g)
constexpr int RED_CHUNKS = 64;
constexpr int NT = NSP / 128;             // 256 n-tiles
constexpr int CTXSZ = NB * NH * HDIM * 33;// 16896

// gemm0 smem layout (floats): K-slice 16, 4 rotating B stages, 512 thr
constexpr int G0_AS   = 0;                // [256][132]          (33792)
constexpr int G0_BS   = 33792;            // [4][16][136]        (8704)
constexpr int G0_ZP   = 42496;            // [128][4]            (512)
constexpr int G0_SMEM = 43008;            // 172032 B
constexpr int G0_EP   = 0;                // epilogue: [128][132]
constexpr int G0_VP   = 16896;            // epilogue: [128][132]

// gemm1 smem layout (floats)
constexpr int G1_AS   = 0;                // [128][132]
constexpr int G1_BS   = 16896;            // [4][16][136]
constexpr int G1_SMEM = 25600;            // 102400 B
}

// ---------------- device scratch ----------------
__device__ float g_part[NB * GRP * RED_CHUNKS * 2];
__device__ float g_W1[NB * QKVC * CH];
__device__ float g_b1[NB * QKVC];
__device__ float g_ctxp[(size_t)NT * CTXSZ];
__device__ float g_ctx2[16 * CTXSZ];
__device__ float g_ctx[CTXSZ];
__device__ float g_M[NB * CH * CH];
__device__ float g_F[NB * CH * CH];
__device__ float g_fb[NB * CH];

// ---------------- helpers ----------------
__device__ __forceinline__ uint32_t f2tf(float f) {
    uint32_t r; asm("cvt.rna.tf32.f32 %0, %1;" : "=r"(r) : "f"(f)); return r;
}
__device__ __forceinline__ float tf32f(float f) {
    return __uint_as_float(f2tf(f));
}
__device__ __forceinline__ void mma8(float* c, uint32_t a0, uint32_t a1,
                                     uint32_t a2, uint32_t a3,
                                     uint32_t b0, uint32_t b1) {
    asm volatile(
        "mma.sync.aligned.m16n8k8.row.col.f32.tf32.tf32.f32 "
        "{%0,%1,%2,%3},{%4,%5,%6,%7},{%8,%9},{%0,%1,%2,%3};"
        : "+f"(c[0]), "+f"(c[1]), "+f"(c[2]), "+f"(c[3])
        : "r"(a0), "r"(a1), "r"(a2), "r"(a3), "r"(b0), "r"(b1));
}
// a0..a3 of tf32 m16n8k8 A-fragment in one instruction
__device__ __forceinline__ void ldsm_x4(uint32_t& d0, uint32_t& d1,
                                        uint32_t& d2, uint32_t& d3, uint32_t addr) {
    asm volatile("ldmatrix.sync.aligned.m8n8.x4.shared.b16 {%0,%1,%2,%3}, [%4];"
                 : "=r"(d0), "=r"(d1), "=r"(d2), "=r"(d3) : "r"(addr));
}
__device__ __forceinline__ void cp_async16(uint32_t smem_byte, const void* g) {
    asm volatile("cp.async.ca.shared.global [%0], [%1], 16;"
                 :: "r"(smem_byte), "l"(g));
}
// streaming variant: L2-only, keeps L1 free for fragment traffic
__device__ __forceinline__ void cp_async16_cg(uint32_t smem_byte, const void* g) {
    asm volatile("cp.async.cg.shared.global [%0], [%1], 16;"
                 :: "r"(smem_byte), "l"(g));
}
__device__ __forceinline__ void cp_commit() {
    asm volatile("cp.async.commit_group;");
}
template <int N>
__device__ __forceinline__ void cp_wait() {
    asm volatile("cp.async.wait_group %0;" :: "n"(N));
}
// wait so that buffer k0 (of 8, last commit at k0=5+3) is retired
__device__ __forceinline__ void cp_wait_for(int k0) {
    if (k0 < 6)      cp_wait<2>();
    else if (k0 == 6) cp_wait<1>();
    else              cp_wait<0>();
}

// ---------------- 0) profiling shim (aligns gemm0 with ncu capture window) ----------------
__global__ void shim_k() {}

// ---------------- 1) groupnorm stats (1024 blocks) ----------------
__global__ void reduce_k(const float* __restrict__ x) {
    int bg = blockIdx.x >> 6;
    int chunk = blockIdx.x & 63;
    const float4* p = reinterpret_cast<const float4*>(
        x + (size_t)bg * GELEM + (size_t)chunk * (GELEM / RED_CHUNKS));
    int t = threadIdx.x;
    float s = 0.f, q = 0.f;
#pragma unroll
    for (int i = 0; i < 16; i++) {
        float4 v = p[t + i * 256];
        s += (v.x + v.y) + (v.z + v.w);
        q += v.x * v.x + v.y * v.y + v.z * v.z + v.w * v.w;
    }
    for (int off = 16; off; off >>= 1) {
        s += __shfl_down_sync(0xffffffffu, s, off);
        q += __shfl_down_sync(0xffffffffu, q, off);
    }
    __shared__ float ss[8], sq[8];
    if ((t & 31) == 0) { ss[t >> 5] = s; sq[t >> 5] = q; }
    __syncthreads();
    if (t == 0) {
        float S = 0.f, Q = 0.f;
        for (int i = 0; i < 8; i++) { S += ss[i]; Q += sq[i]; }
        g_part[blockIdx.x * 2]     = S;
        g_part[blockIdx.x * 2 + 1] = Q;
    }
}

// ---------------- 2) fold gn into qkv weight/bias (W tf32-RNA pre-rounded) ----------------
__global__ void prep_k(const float* __restrict__ qkvw,
                       const float* __restrict__ gnw,
                       const float* __restrict__ gnb) {
    int o = blockIdx.x, b = blockIdx.y, c = threadIdx.x;
    int g = c >> 5;
    int bg = b * GRP + g;
    float S = 0.f, Q = 0.f;
#pragma unroll 8
    for (int ch = 0; ch < RED_CHUNKS; ch++) {
        S += g_part[(bg * RED_CHUNKS + ch) * 2];
        Q += g_part[(bg * RED_CHUNKS + ch) * 2 + 1];
    }
    const float inv = 1.0f / (float)GELEM;
    float mean = S * inv;
    float var  = Q * inv - mean * mean;
    float rstd = rsqrtf(var + 1e-5f);
    float s = rstd * gnw[c];
    float t = gnb[c] - mean * s;
    float w = qkvw[o * CH + c];
    g_W1[(b * QKVC + o) * CH + c] = tf32f(w * s);
    __shared__ float red[CH];
    red[c] = w * t;
    __syncthreads();
    for (int off = 64; off; off >>= 1) {
        if (c < off) red[c] += red[c + off];
        __syncthreads();
    }
    if (c == 0) g_b1[b * QKVC + o] = red[0];
}

// ---------------- 3) fused kv-gemm + exp + ctx partials (512 thr, ldsm) ----------------
__global__ void __launch_bounds__(512) gemm0_k(const float* __restrict__ x) {
    extern __shared__ float smem[];
    float* As = smem + G0_AS;
    float* Bs = smem + G0_BS;
    float* Zp = smem + G0_ZP;
    float* Ep = smem + G0_EP;
    float* Vp = smem + G0_VP;

    int b = blockIdx.z;
    int tN = blockIdx.x * 128;
    const float* A = g_W1 + (size_t)(b * QKVC + CH) * CH;   // k,v rows (tf32 pre-rounded)
    const float* B = x + (size_t)b * CH * NSP;
    int tid = threadIdx.x, lane = tid & 31, w = tid >> 5;   // w: 0..15
    int wm = w >> 2, wn = w & 3;               // 4 m-rows x 4 n-cols
    int q = lane >> 2, m = lane & 3;

    uint32_t as_b = (uint32_t)__cvta_generic_to_shared(As);
    uint32_t bs_b = (uint32_t)__cvta_generic_to_shared(Bs);

    // A preload via cp.async (.ca: W1 is re-read by later waves on this SM)
#pragma unroll 4
    for (int i = 0; i < 16; i++) {
        int f = tid + i * 512;
        int r = f >> 5, c4 = (f & 31) * 4;
        cp_async16(as_b + (uint32_t)(r * 132 + c4) * 4u, &A[r * CH + c4]);
    }

    int br = tid >> 5, bc = (tid & 31) * 4;     // 512 thr -> one float4 each
#define CPB(t) do { int kr = (t) * 16; uint32_t dst = bs_b + (uint32_t)(((t) & 3) * 2176) * 4u; \
        cp_async16_cg(dst + (uint32_t)(br * 136 + bc) * 4u, &B[(size_t)(kr + br) * NSP + tN + bc]); } while (0)

    CPB(0); cp_commit();          // group0 = A + B0
    CPB(1); cp_commit();
    CPB(2); cp_commit();

    // ldmatrix lane addressing: row = r0 + (lane&15), col = (lane>>4)*4
    int rl = lane & 15, cl = (lane >> 4) * 4;
    uint32_t aaddr[4];
#pragma unroll
    for (int mt = 0; mt < 4; mt++)
        aaddr[mt] = as_b + (uint32_t)((wm * 64 + mt * 16 + rl) * 132 + cl) * 4u;

    float acc[4][4][4];
#pragma unroll
    for (int mt = 0; mt < 4; mt++)
#pragma unroll
        for (int nt = 0; nt < 4; nt++)
#pragma unroll
            for (int i = 0; i < 4; i++) acc[mt][nt][i] = 0.f;

#pragma unroll
    for (int k0 = 0; k0 < 8; k0++) {
        cp_wait_for(k0);
        __syncthreads();
        if (k0 < 5) { CPB(k0 + 3); cp_commit(); }
        const float* Bb = Bs + (k0 & 3) * 2176;
#pragma unroll
        for (int ks = 0; ks < 16; ks += 8) {
            uint32_t a[4][4];
#pragma unroll
            for (int mt = 0; mt < 4; mt++)
                ldsm_x4(a[mt][0], a[mt][1], a[mt][2], a[mt][3],
                        aaddr[mt] + (uint32_t)(k0 * 16 + ks) * 4u);
#pragma unroll
            for (int nt = 0; nt < 4; nt++) {
                int col = wn * 32 + nt * 8 + q;
                uint32_t b0 = f2tf(Bb[(ks + m) * 136 + col]);
                uint32_t b1 = f2tf(Bb[(ks + 4 + m) * 136 + col]);
#pragma unroll
                for (int mt = 0; mt < 4; mt++)
                    mma8(acc[mt][nt], a[mt][0], a[mt][1], a[mt][2], a[mt][3], b0, b1);
            }
        }
    }
#undef CPB

    // bias (+exp on k rows) + Z partials from registers
    const float* bias = g_b1 + b * QKVC + CH;
    float zlo[4], zhi[4];
#pragma unroll
    for (int mt = 0; mt < 4; mt++) {
        int r0 = wm * 64 + mt * 16 + q;
        float bv0 = bias[r0], bv1 = bias[r0 + 8];
        zlo[mt] = 0.f; zhi[mt] = 0.f;
#pragma unroll
        for (int nt = 0; nt < 4; nt++) {
            if (wm < 2) {   // k rows -> exp
                acc[mt][nt][0] = __expf(acc[mt][nt][0] + bv0);
                acc[mt][nt][1] = __expf(acc[mt][nt][1] + bv0);
                acc[mt][nt][2] = __expf(acc[mt][nt][2] + bv1);
                acc[mt][nt][3] = __expf(acc[mt][nt][3] + bv1);
                zlo[mt] += acc[mt][nt][0] + acc[mt][nt][1];
                zhi[mt] += acc[mt][nt][2] + acc[mt][nt][3];
            } else {        // v rows
                acc[mt][nt][0] += bv0; acc[mt][nt][1] += bv0;
                acc[mt][nt][2] += bv1; acc[mt][nt][3] += bv1;
            }
        }
        if (wm < 2) {       // quad-reduce across the 4 col-lanes
            zlo[mt] += __shfl_xor_sync(0xffffffffu, zlo[mt], 1);
            zlo[mt] += __shfl_xor_sync(0xffffffffu, zlo[mt], 2);
            zhi[mt] += __shfl_xor_sync(0xffffffffu, zhi[mt], 1);
            zhi[mt] += __shfl_xor_sync(0xffffffffu, zhi[mt], 2);
        }
    }

    __syncthreads();        // As dead; reuse as Ep/Vp

    // scatter E (exp(k), tf32-rounded), V (tf32-rounded), Z partials
#pragma unroll
    for (int mt = 0; mt < 4; mt++) {
        int r = wm * 64 + mt * 16 + q;          // 0..255
        float* T = (r < 128) ? (Ep + r * 132) : (Vp + (r - 128) * 132);
#pragma unroll
        for (int nt = 0; nt < 4; nt++) {
            int cc = wn * 32 + nt * 8 + 2 * m;
            float2 lo = make_float2(tf32f(acc[mt][nt][0]), tf32f(acc[mt][nt][1]));
            float2 hi = make_float2(tf32f(acc[mt][nt][2]), tf32f(acc[mt][nt][3]));
            *reinterpret_cast<float2*>(T + cc)           = lo;
            *reinterpret_cast<float2*>(T + 8 * 132 + cc) = hi;
        }
        if (wm < 2 && m == 0) {
            Zp[r * 4 + wn]       = zlo[mt];
            Zp[(r + 8) * 4 + wn] = zhi[mt];
        }
    }
    __syncthreads();

    float* pbase = g_ctxp + (size_t)blockIdx.x * CTXSZ;

    // Z: combine the four col-stripe partials, write
    if (tid < 128) {
        int h = tid >> 5, d = tid & 31;
        pbase[(size_t)((b * NH + h) * HDIM + d) * 33 + 32] =
            (Zp[tid * 4] + Zp[tid * 4 + 1]) + (Zp[tid * 4 + 2] + Zp[tid * 4 + 3]);
    }

    // ctx mma on warps 0..7: warp w -> head (w>>1), row-half (w&1): 16(d) x 32(e), K=128
    if (w < 8) {
        int h = w >> 1, mh = w & 1;
        const float* Eh = Ep + h * 32 * 132;
        const float* Vh = Vp + h * 32 * 132;
        float c4[4][4];
#pragma unroll
        for (int nt = 0; nt < 4; nt++)
#pragma unroll
            for (int i = 0; i < 4; i++) c4[nt][i] = 0.f;
#pragma unroll
        for (int ks = 0; ks < 128; ks += 8) {
            int ar = mh * 16 + q;
            uint32_t a0 = __float_as_uint(Eh[ar * 132 + ks + m]);
            uint32_t a1 = __float_as_uint(Eh[(ar + 8) * 132 + ks + m]);
            uint32_t a2 = __float_as_uint(Eh[ar * 132 + ks + m + 4]);
            uint32_t a3 = __float_as_uint(Eh[(ar + 8) * 132 + ks + m + 4]);
#pragma unroll
            for (int nt = 0; nt < 4; nt++) {
                int ec = nt * 8 + q;
                uint32_t b0 = __float_as_uint(Vh[ec * 132 + ks + m]);
                uint32_t b1 = __float_as_uint(Vh[ec * 132 + ks + 4 + m]);
                mma8(c4[nt], a0, a1, a2, a3, b0, b1);
            }
        }
        float* ph = pbase + (size_t)((b * NH + h) * HDIM) * 33;
        int dr = mh * 16 + q;
#pragma unroll
        for (int nt = 0; nt < 4; nt++) {
            int ec = nt * 8 + 2 * m;
            ph[dr * 33 + ec]           = c4[nt][0];
            ph[dr * 33 + ec + 1]       = c4[nt][1];
            ph[(dr + 8) * 33 + ec]     = c4[nt][2];
            ph[(dr + 8) * 33 + ec + 1] = c4[nt][3];
        }
    }
}

// ---------------- 4) combine ctx partials: two stages (16-way, scalar) ----------------
__global__ void combineA_k() {
    int t = blockIdx.x * 256 + threadIdx.x;
    int g = blockIdx.y;
    const float* p = g_ctxp + (size_t)(g * 16) * CTXSZ + t;
    float s0 = 0.f, s1 = 0.f, s2 = 0.f, s3 = 0.f;
#pragma unroll
    for (int c = 0; c < 16; c += 4) {
        s0 += p[(size_t)c * CTXSZ];
        s1 += p[(size_t)(c + 1) * CTXSZ];
        s2 += p[(size_t)(c + 2) * CTXSZ];
        s3 += p[(size_t)(c + 3) * CTXSZ];
    }
    g_ctx2[g * CTXSZ + t] = (s0 + s1) + (s2 + s3);
}
__global__ void combineB_k() {
    int t = blockIdx.x * 256 + threadIdx.x;
    float s = 0.f;
#pragma unroll
    for (int g = 0; g < 16; g++) s += g_ctx2[g * CTXSZ + t];
    g_ctx[t] = s;
}

// ---------------- 5) M = out_w folded through normalized ctx ----------------
__global__ void fold1_k(const float* __restrict__ outw) {
    int o = blockIdx.x, b = blockIdx.y, hd = threadIdx.x;
    int h = hd >> 5, d = hd & 31;
    __shared__ float sOW[CH];
    sOW[hd] = outw[o * CH + hd];
    __syncthreads();
    const float* nm = g_ctx + (size_t)((b * NH + h) * HDIM + d) * 33;
    float acc = 0.f;
#pragma unroll
    for (int e = 0; e < HDIM; e++) acc += sOW[h * HDIM + e] * nm[e];
    g_M[(b * CH + o) * CH + hd] = acc / nm[32];
}

// ---------------- 6) F = M @ Wq' (tf32 pre-rounded), fb = M @ bq' + out_bias ----------------
__global__ void fold2_k(const float* __restrict__ outb) {
    int o = blockIdx.x, b = blockIdx.y, c = threadIdx.x;
    __shared__ float sM[CH];
    __shared__ float red[CH];
    sM[c] = g_M[(size_t)(b * CH + o) * CH + c];
    __syncthreads();
    const float* Wq = g_W1 + (size_t)b * QKVC * CH;
    float acc = 0.f;
#pragma unroll 8
    for (int k = 0; k < CH; k++) acc += sM[k] * Wq[k * CH + c];
    g_F[(size_t)(b * CH + o) * CH + c] = tf32f(acc);
    red[c] = sM[c] * g_b1[b * QKVC + c];
    __syncthreads();
    for (int off = 64; off; off >>= 1) {
        if (c < off) red[c] += red[c + off];
        __syncthreads();
    }
    if (c == 0) g_fb[b * CH + o] = red[0] + outb[o];
}

// ---------------- 7) out = F @ x + fb + x ----------------
__global__ void __launch_bounds__(256, 2) gemm1_k(const float* __restrict__ x,
                                                  float* __restrict__ out) {
    extern __shared__ float smem[];
    float* As = smem + G1_AS;
    float* Bs = smem + G1_BS;

    int b = blockIdx.z;
    int tN = blockIdx.x * 128;
    const float* A = g_F + (size_t)b * CH * CH;   // tf32 pre-rounded
    const float* B = x + (size_t)b * CH * NSP;
    float* Co = out + (size_t)b * CH * NSP;
    int tid = threadIdx.x, lane = tid & 31, w = tid >> 5;
    int wm = w >> 2, wn = w & 3;               // 2 m-halves x 4 n-cols
    int q = lane >> 2, m = lane & 3;

    uint32_t as_b = (uint32_t)__cvta_generic_to_shared(As);
    uint32_t bs_b = (uint32_t)__cvta_generic_to_shared(Bs);

    // A preload via cp.async (.ca: g_F re-read across waves)
#pragma unroll 4
    for (int i = 0; i < 16; i++) {
        int f = tid + i * 256;
        int r = f >> 5, c4 = (f & 31) * 4;
        cp_async16(as_b + (uint32_t)(r * 132 + c4) * 4u, &A[r * CH + c4]);
    }

    int br0 = tid >> 5, bc0 = (tid & 31) * 4;
    int br1 = (tid + 256) >> 5;
#define CPB(t) do { int kr = (t) * 16; uint32_t dst = bs_b + (uint32_t)(((t) & 3) * 2176) * 4u; \
        cp_async16_cg(dst + (uint32_t)(br0 * 136 + bc0) * 4u, &B[(size_t)(kr + br0) * NSP + tN + bc0]); \
        cp_async16_cg(dst + (uint32_t)(br1 * 136 + bc0) * 4u, &B[(size_t)(kr + br1) * NSP + tN + bc0]); } while (0)

    CPB(0); cp_commit();
    CPB(1); cp_commit();
    CPB(2); cp_commit();

    int rl = lane & 15, cl = (lane >> 4) * 4;
    uint32_t aaddr[4];
#pragma unroll
    for (int mt = 0; mt < 4; mt++)
        aaddr[mt] = as_b + (uint32_t)((wm * 64 + mt * 16 + rl) * 132 + cl) * 4u;

    float acc[4][4][4];
#pragma unroll
    for (int mt = 0; mt < 4; mt++)
#pragma unroll
        for (int nt = 0; nt < 4; nt++)
#pragma unroll
            for (int i = 0; i < 4; i++) acc[mt][nt][i] = 0.f;

#pragma unroll
    for (int k0 = 0; k0 < 8; k0++) {
        cp_wait_for(k0);
        __syncthreads();
        if (k0 < 5) { CPB(k0 + 3); cp_commit(); }
        const float* Bb = Bs + (k0 & 3) * 2176;
#pragma unroll
        for (int ks = 0; ks < 16; ks += 8) {
            uint32_t a[4][4];
#pragma unroll
            for (int mt = 0; mt < 4; mt++)
                ldsm_x4(a[mt][0], a[mt][1], a[mt][2], a[mt][3],
                        aaddr[mt] + (uint32_t)(k0 * 16 + ks) * 4u);
#pragma unroll
            for (int nt = 0; nt < 4; nt++) {
                int col = wn * 32 + nt * 8 + q;
                uint32_t b0 = f2tf(Bb[(ks + m) * 136 + col]);
                uint32_t b1 = f2tf(Bb[(ks + 4 + m) * 136 + col]);
#pragma unroll
                for (int mt = 0; mt < 4; mt++)
                    mma8(acc[mt][nt], a[mt][0], a[mt][1], a[mt][2], a[mt][3], b0, b1);
            }
        }
    }
#undef CPB

    // epilogue: residual rows 64..127 still live in B stage buffers (k0=4..7 -> buf 0..3)
#pragma unroll
    for (int mt = 0; mt < 4; mt++) {
        int r0 = wm * 64 + mt * 16 + q;
        float bv0 = g_fb[b * CH + r0], bv1 = g_fb[b * CH + r0 + 8];
#pragma unroll
        for (int nt = 0; nt < 4; nt++) {
            int cc = wn * 32 + nt * 8 + 2 * m;
            size_t o0 = (size_t)r0 * NSP + tN + cc;
            size_t o1 = (size_t)(r0 + 8) * NSP + tN + cc;
            float2 x0, x1;
            if (wm == 1) {   // rows 64..127: read residual from smem (bit-identical)
                const float* Sb = Bs + ((r0 >> 4) & 3) * 2176;
                x0 = *reinterpret_cast<const float2*>(Sb + (r0 & 15) * 136 + cc);
                x1 = *reinterpret_cast<const float2*>(Sb + ((r0 & 15) + 8) * 136 + cc);
            } else {
                x0 = *reinterpret_cast<const float2*>(&B[o0]);
                x1 = *reinterpret_cast<const float2*>(&B[o1]);
            }
            float2 r0v = { acc[mt][nt][0] + bv0 + x0.x, acc[mt][nt][1] + bv0 + x0.y };
            float2 r1v = { acc[mt][nt][2] + bv1 + x1.x, acc[mt][nt][3] + bv1 + x1.y };
            *reinterpret_cast<float2*>(&Co[o0]) = r0v;
            *reinterpret_cast<float2*>(&Co[o1]) = r1v;
        }
    }
}

// ---------------- launch ----------------
extern "C" void kernel_launch(void* const* d_in, const int* in_sizes, int n_in,
                              void* d_out, int out_size) {
    (void)in_sizes; (void)n_in; (void)out_size;
    const float* x    = (const float*)d_in[0];
    const float* gnw  = (const float*)d_in[1];
    const float* gnb  = (const float*)d_in[2];
    const float* qkvw = (const float*)d_in[3];
    const float* outw = (const float*)d_in[4];
    const float* outb = (const float*)d_in[5];
    float* out = (float*)d_out;

    cudaFuncSetAttribute(gemm0_k, cudaFuncAttributeMaxDynamicSharedMemorySize,
                         G0_SMEM * sizeof(float));
    cudaFuncSetAttribute(gemm1_k, cudaFuncAttributeMaxDynamicSharedMemorySize,
                         G1_SMEM * sizeof(float));

    reduce_k<<<NB * GRP * RED_CHUNKS, 256>>>(x);
    prep_k<<<dim3(QKVC, NB), CH>>>(qkvw, gnw, gnb);
    shim_k<<<1, 32>>>();      // aligns gemm0 with ncu's fixed capture window
    gemm0_k<<<dim3(NT, 1, NB), 512, G0_SMEM * sizeof(float)>>>(x);
    combineA_k<<<dim3(CTXSZ / 256, 16), 256>>>();
    combineB_k<<<CTXSZ / 256, 256>>>();
    fold1_k<<<dim3(CH, NB), CH>>>(outw);
    fold2_k<<<dim3(CH, NB), CH>>>(outb);
    gemm1_k<<<dim3(NT, 1, NB), 256, G1_SMEM * sizeof(float)>>>(x, out);
}